// round 9
// baseline (speedup 1.0000x reference)
#include <cuda_runtime.h>
#include <math.h>
#include <stdint.h>

// Problem dims (fixed by the dataset)
#define T    2048
#define D    512
#define H    1024
#define H2   2048
#define E    8
#define NSLOT (T*2)   // 4096

// ---------------- scratch (device globals; no allocations allowed) ----------
__device__ int   g_count[E];
__device__ int   g_off[E];
__device__ int   g_list[E*T];        // per-expert token slot lists (slot = t*2+k)
__device__ float g_gate[NSLOT];      // gate value per slot
__device__ float g_probs[E];         // sum of softmax probs per expert (aux loss)
__device__ float g_lsesq;            // sum of lse^2 (aux loss)
__device__ float g_yslot[(size_t)NSLOT*D];   // gate-scaled expert outputs per slot

// pre-split operands: interleaved {tf32_hi, tf32_lo} pairs
__device__ uint2 g_x2[(size_t)T*D];
__device__ uint2 g_win2[(size_t)E*D*H2];
__device__ uint2 g_wout2[(size_t)E*H*D];
__device__ uint2 g_hidden2[(size_t)NSLOT*H];

// ======================= helpers =============================================
__device__ __forceinline__ uint32_t smem_u32(const void* p) {
    uint32_t a;
    asm("{ .reg .u64 t; cvta.to.shared.u64 t, %1; cvt.u32.u64 %0, t; }" : "=r"(a) : "l"(p));
    return a;
}
#define CP16(dst, src) \
    asm volatile("cp.async.cg.shared.global [%0], [%1], 16;" :: "r"(dst), "l"(src) : "memory")
#define CP_COMMIT() asm volatile("cp.async.commit_group;" ::: "memory")
#define CP_WAIT2()  asm volatile("cp.async.wait_group 2;" ::: "memory")

__device__ __forceinline__ void split_tf32(float x, uint32_t& hi, uint32_t& lo) {
    asm("cvt.rna.tf32.f32 %0, %1;" : "=r"(hi) : "f"(x));
    float lf = x - __uint_as_float(hi);
    asm("cvt.rna.tf32.f32 %0, %1;" : "=r"(lo) : "f"(lf));
}

#define MMA_TF32(d, a, b0, b1) \
    asm volatile("mma.sync.aligned.m16n8k8.row.col.f32.tf32.tf32.f32 " \
        "{%0,%1,%2,%3},{%4,%5,%6,%7},{%8,%9},{%0,%1,%2,%3};" \
        : "+f"((d)[0]), "+f"((d)[1]), "+f"((d)[2]), "+f"((d)[3]) \
        : "r"((a)[0]), "r"((a)[1]), "r"((a)[2]), "r"((a)[3]), "r"(b0), "r"(b1))

// ---------------- operand pre-split (streaming, vectorized) -----------------
__global__ __launch_bounds__(256) void k_split(const float4* __restrict__ src,
                                               uint4* __restrict__ dst, int n4) {
    int i = blockIdx.x * 256 + threadIdx.x;
    if (i >= n4) return;
    float4 v = src[i];
    uint4 o0, o1;
    split_tf32(v.x, o0.x, o0.y);
    split_tf32(v.y, o0.z, o0.w);
    split_tf32(v.z, o1.x, o1.y);
    split_tf32(v.w, o1.z, o1.w);
    dst[i*2+0] = o0;
    dst[i*2+1] = o1;
}

// ---------------- zero-init (graph replays must reset state) ----------------
__global__ void k_zero() {
    int t = threadIdx.x;
    if (t < E) { g_count[t] = 0; g_probs[t] = 0.f; }
    if (t == 0) g_lsesq = 0.f;
}

// ---------------- router: logits, top-2, gates, scatter, loss partials ------
__global__ __launch_bounds__(256) void k_router(const float* __restrict__ x,
                                                const float* __restrict__ wr) {
    __shared__ float sw[D*E];
    __shared__ float sp[E];
    __shared__ float slse;
    const int tid = threadIdx.x;
    for (int i = tid; i < D*E; i += 256) sw[i] = wr[i];
    if (tid < E) sp[tid] = 0.f;
    if (tid == 0) slse = 0.f;
    __syncthreads();

    const int t = blockIdx.x * 256 + tid;
    float l[E];
#pragma unroll
    for (int j = 0; j < E; j++) l[j] = 0.f;
    const float4* xr4 = reinterpret_cast<const float4*>(x + (size_t)t * D);
    for (int d4 = 0; d4 < D/4; d4++) {
        float4 v = xr4[d4];
        int d = d4 * 4;
#pragma unroll
        for (int j = 0; j < E; j++) {
            l[j] = fmaf(v.x, sw[(d+0)*E + j], l[j]);
            l[j] = fmaf(v.y, sw[(d+1)*E + j], l[j]);
            l[j] = fmaf(v.z, sw[(d+2)*E + j], l[j]);
            l[j] = fmaf(v.w, sw[(d+3)*E + j], l[j]);
        }
    }

    // top-2, matching jax.lax.top_k tie rule (earliest index wins)
    int i1 = 0; float v1 = l[0];
#pragma unroll
    for (int j = 1; j < E; j++) if (l[j] > v1) { v1 = l[j]; i1 = j; }
    int i2 = (i1 == 0) ? 1 : 0; float v2 = l[i2];
#pragma unroll
    for (int j = 0; j < E; j++) if (j != i1 && l[j] > v2) { v2 = l[j]; i2 = j; }

    float e2 = expf(v2 - v1);
    float inv = 1.f / (1.f + e2);
    float g1 = inv;
    float g2 = e2 * inv;

    float m = v1;
    float s = 0.f;
#pragma unroll
    for (int j = 0; j < E; j++) s += expf(l[j] - m);
    float lse = m + logf(s);
    atomicAdd(&slse, lse * lse);
    float invs = 1.f / s;
#pragma unroll
    for (int j = 0; j < E; j++) atomicAdd(&sp[j], expf(l[j] - m) * invs);

    int p1 = atomicAdd(&g_count[i1], 1);
    g_list[i1*T + p1] = t*2 + 0;
    g_gate[t*2 + 0] = g1;
    int p2 = atomicAdd(&g_count[i2], 1);
    g_list[i2*T + p2] = t*2 + 1;
    g_gate[t*2 + 1] = g2;

    __syncthreads();
    if (tid < E) atomicAdd(&g_probs[tid], sp[tid]);
    if (tid == 0) atomicAdd(&g_lsesq, slse);
}

// ---------------- prefix offsets over E=8 -----------------------------------
__global__ void k_offsets() {
    int o = 0;
    for (int e = 0; e < E; e++) { g_off[e] = o; o += g_count[e]; }
}

// ============================================================================
// GEMM1 (mma.sync tf32, 3x split, pre-split operands) fused with GLU.
// CTA: 128 gathered tokens x 128 h-cols + matching 128 gate-cols. K=512,
// chunks of 16, 3-stage cp.async pipeline.
// SMEM per stage: A uint2[128][18] (pad 2), B uint2[16][258] (pad 2;
// cols 0..127 = h half, 128..255 = gate half).
// ============================================================================
#define AST 18
#define BST1 258
#define G1_A_STG (128*AST*8)             // 18432
#define G1_B_STG (16*BST1*8)             // 33024
#define G1_SMEM  (3*(G1_A_STG + G1_B_STG))

__global__ __launch_bounds__(256, 1) void k_gemm1(const float* __restrict__ xunused) {
    const int e   = blockIdx.x >> 4;
    const int rt  = blockIdx.x & 15;
    const int cnt = g_count[e];
    const int m0  = rt * 128;
    if (m0 >= cnt) return;
    const int off = g_off[e];
    const int n0  = blockIdx.y * 128;

    extern __shared__ char smem[];
    __shared__ int s_tok[128];
    uint2* sA[3]; uint2* sB[3];
#pragma unroll
    for (int s = 0; s < 3; s++) {
        sA[s] = (uint2*)(smem + s*G1_A_STG);
        sB[s] = (uint2*)(smem + 3*G1_A_STG + s*G1_B_STG);
    }

    const int tid  = threadIdx.x;
    const int wid  = tid >> 5;
    const int lane = tid & 31;
    const int wm   = wid & 3;        // m offset wm*32
    const int wn   = wid >> 2;       // n offset wn*64

    if (tid < 128) {
        int i = m0 + tid;
        s_tok[tid] = g_list[e*T + min(i, cnt-1)] >> 1;
    }
    __syncthreads();

    const uint2* W = g_win2 + (size_t)e * D * H2;

    auto load_stage = [&](int it, int buf) {
        const int d0 = it * 16;
        uint2* a = sA[buf];
#pragma unroll
        for (int r = 0; r < 4; r++) {        // A: 1024 cp16 (2 uint2 each)
            int i = tid + r*256;
            int row = i >> 3, q = i & 7;
            uint32_t dst = smem_u32(a + row*AST + q*2);
            CP16(dst, g_x2 + (size_t)s_tok[row]*D + d0 + q*2);
        }
        uint2* b = sB[buf];
#pragma unroll
        for (int r = 0; r < 8; r++) {        // B: 2048 cp16
            int i = tid + r*256;
            int k = i >> 7, c = i & 127;
            int n = c * 2;
            int gc = (n < 128) ? (n0 + n) : (H + n0 + (n - 128));
            uint32_t dst = smem_u32(b + k*BST1 + n);
            CP16(dst, W + (size_t)(d0 + k)*H2 + gc);
        }
        CP_COMMIT();
    };

    float acc[2][8][2][4];
#pragma unroll
    for (int h2 = 0; h2 < 2; h2++)
#pragma unroll
        for (int nf = 0; nf < 8; nf++)
#pragma unroll
            for (int mf = 0; mf < 2; mf++)
#pragma unroll
                for (int r = 0; r < 4; r++) acc[h2][nf][mf][r] = 0.f;

    const int NIT = D / 16;   // 32
    load_stage(0, 0);
    load_stage(1, 1);
    load_stage(2, 2);

    const int rA = wm*32 + (lane >> 2);
    const int kA = lane & 3;
    const int nB = wn*64 + (lane >> 2);

    int buf = 0;
    for (int it = 0; it < NIT; it++) {
        CP_WAIT2();
        __syncthreads();
        const uint2* a = sA[buf];
        const uint2* b = sB[buf];
#pragma unroll
        for (int ks = 0; ks < 2; ks++) {
            const int k0 = ks * 8;
            uint2 af[2][4];
#pragma unroll
            for (int mf = 0; mf < 2; mf++) {
                int rr = rA + mf*16;
                af[mf][0] = a[(rr  )*AST + k0 + kA    ];
                af[mf][1] = a[(rr+8)*AST + k0 + kA    ];
                af[mf][2] = a[(rr  )*AST + k0 + kA + 4];
                af[mf][3] = a[(rr+8)*AST + k0 + kA + 4];
            }
            uint32_t ahi[2][4], alo[2][4];
#pragma unroll
            for (int mf = 0; mf < 2; mf++)
#pragma unroll
                for (int q = 0; q < 4; q++) { ahi[mf][q] = af[mf][q].x; alo[mf][q] = af[mf][q].y; }
#pragma unroll
            for (int h2 = 0; h2 < 2; h2++) {
#pragma unroll
                for (int nf = 0; nf < 8; nf++) {
                    int n = h2*128 + nB + nf*8;
                    uint2 b0 = b[(k0 + kA    )*BST1 + n];
                    uint2 b1 = b[(k0 + kA + 4)*BST1 + n];
                    MMA_TF32(acc[h2][nf][0], ahi[0], b0.x, b1.x);
                    MMA_TF32(acc[h2][nf][1], ahi[1], b0.x, b1.x);
                    MMA_TF32(acc[h2][nf][0], ahi[0], b0.y, b1.y);
                    MMA_TF32(acc[h2][nf][1], ahi[1], b0.y, b1.y);
                    MMA_TF32(acc[h2][nf][0], alo[0], b0.x, b1.x);
                    MMA_TF32(acc[h2][nf][1], alo[1], b0.x, b1.x);
                }
            }
        }
        __syncthreads();
        if (it + 3 < NIT) load_stage(it + 3, buf);
        buf = (buf == 2) ? 0 : buf + 1;
    }

    // Epilogue: h = silu(a)*g, split, write g_hidden2
#pragma unroll
    for (int mf = 0; mf < 2; mf++) {
#pragma unroll
        for (int rr = 0; rr < 2; rr++) {
            int m = m0 + wm*32 + mf*16 + (lane >> 2) + rr*8;
            if (m < cnt) {
                uint2* drow = g_hidden2 + (size_t)(off + m)*H + n0;
#pragma unroll
                for (int nf = 0; nf < 8; nf++) {
                    int col = wn*64 + nf*8 + 2*(lane & 3);
                    float a0 = acc[0][nf][mf][rr*2+0], g0v = acc[1][nf][mf][rr*2+0];
                    float a1 = acc[0][nf][mf][rr*2+1], g1v = acc[1][nf][mf][rr*2+1];
                    float h0 = (a0 / (1.f + expf(-a0))) * g0v;
                    float h1 = (a1 / (1.f + expf(-a1))) * g1v;
                    uint4 o;
                    split_tf32(h0, o.x, o.y);
                    split_tf32(h1, o.z, o.w);
                    *reinterpret_cast<uint4*>(drow + col) = o;
                }
            }
        }
    }
}

// ============================================================================
// GEMM2 (mma.sync tf32, 3x split, pre-split): yslot = gate * (hidden @ w_out)
// CTA: 128 slots x 128 out-cols. K=1024, chunks of 16, 3-stage pipeline.
// ============================================================================
#define BST2 130
#define G2_A_STG (128*AST*8)             // 18432
#define G2_B_STG (16*BST2*8)             // 16640
#define G2_SMEM  (3*(G2_A_STG + G2_B_STG))

__global__ __launch_bounds__(256, 1) void k_gemm2(const float* __restrict__ unused) {
    const int e   = blockIdx.x >> 4;
    const int rt  = blockIdx.x & 15;
    const int cnt = g_count[e];
    const int m0  = rt * 128;
    if (m0 >= cnt) return;
    const int off = g_off[e];
    const int n0  = blockIdx.y * 128;
    const int cmax = cnt - 1;

    extern __shared__ char smem[];
    uint2* sA[3]; uint2* sB[3];
#pragma unroll
    for (int s = 0; s < 3; s++) {
        sA[s] = (uint2*)(smem + s*G2_A_STG);
        sB[s] = (uint2*)(smem + 3*G2_A_STG + s*G2_B_STG);
    }

    const int tid  = threadIdx.x;
    const int wid  = tid >> 5;
    const int lane = tid & 31;
    const int wm   = wid & 3;
    const int wn   = wid >> 2;

    const uint2* W = g_wout2 + (size_t)e * H * D;

    auto load_stage = [&](int it, int buf) {
        const int h0 = it * 16;
        uint2* a = sA[buf];
#pragma unroll
        for (int r = 0; r < 4; r++) {
            int i = tid + r*256;
            int row = i >> 3, q = i & 7;
            int gr = off + min(m0 + row, cmax);
            uint32_t dst = smem_u32(a + row*AST + q*2);
            CP16(dst, g_hidden2 + (size_t)gr*H + h0 + q*2);
        }
        uint2* b = sB[buf];
#pragma unroll
        for (int r = 0; r < 4; r++) {        // B: 1024 cp16
            int i = tid + r*256;
            int k = i >> 6, c = i & 63;
            int n = c * 2;
            uint32_t dst = smem_u32(b + k*BST2 + n);
            CP16(dst, W + (size_t)(h0 + k)*D + n0 + n);
        }
        CP_COMMIT();
    };

    float acc[8][2][4];
#pragma unroll
    for (int nf = 0; nf < 8; nf++)
#pragma unroll
        for (int mf = 0; mf < 2; mf++)
#pragma unroll
            for (int r = 0; r < 4; r++) acc[nf][mf][r] = 0.f;

    const int NIT = H / 16;   // 64
    load_stage(0, 0);
    load_stage(1, 1);
    load_stage(2, 2);

    const int rA = wm*32 + (lane >> 2);
    const int kA = lane & 3;
    const int nB = wn*64 + (lane >> 2);

    int buf = 0;
    for (int it = 0; it < NIT; it++) {
        CP_WAIT2();
        __syncthreads();
        const uint2* a = sA[buf];
        const uint2* b = sB[buf];
#pragma unroll
        for (int ks = 0; ks < 2; ks++) {
            const int k0 = ks * 8;
            uint2 af[2][4];
#pragma unroll
            for (int mf = 0; mf < 2; mf++) {
                int rr = rA + mf*16;
                af[mf][0] = a[(rr  )*AST + k0 + kA    ];
                af[mf][1] = a[(rr+8)*AST + k0 + kA    ];
                af[mf][2] = a[(rr  )*AST + k0 + kA + 4];
                af[mf][3] = a[(rr+8)*AST + k0 + kA + 4];
            }
            uint32_t ahi[2][4], alo[2][4];
#pragma unroll
            for (int mf = 0; mf < 2; mf++)
#pragma unroll
                for (int q = 0; q < 4; q++) { ahi[mf][q] = af[mf][q].x; alo[mf][q] = af[mf][q].y; }
#pragma unroll
            for (int nf = 0; nf < 8; nf++) {
                int n = nB + nf*8;
                uint2 b0 = b[(k0 + kA    )*BST2 + n];
                uint2 b1 = b[(k0 + kA + 4)*BST2 + n];
                MMA_TF32(acc[nf][0], ahi[0], b0.x, b1.x);
                MMA_TF32(acc[nf][1], ahi[1], b0.x, b1.x);
                MMA_TF32(acc[nf][0], ahi[0], b0.y, b1.y);
                MMA_TF32(acc[nf][1], ahi[1], b0.y, b1.y);
                MMA_TF32(acc[nf][0], alo[0], b0.x, b1.x);
                MMA_TF32(acc[nf][1], alo[1], b0.x, b1.x);
            }
        }
        __syncthreads();
        if (it + 3 < NIT) load_stage(it + 3, buf);
        buf = (buf == 2) ? 0 : buf + 1;
    }

    // Epilogue: scale by gate, scatter to yslot
#pragma unroll
    for (int mf = 0; mf < 2; mf++) {
#pragma unroll
        for (int rr = 0; rr < 2; rr++) {
            int m = m0 + wm*32 + mf*16 + (lane >> 2) + rr*8;
            if (m < cnt) {
                int slot = g_list[e*T + m];
                float gv = g_gate[slot];
                float* drow = g_yslot + (size_t)slot*D + n0;
#pragma unroll
                for (int nf = 0; nf < 8; nf++) {
                    int col = wn*64 + nf*8 + 2*(lane & 3);
                    float2 o;
                    o.x = gv * acc[nf][mf][rr*2+0];
                    o.y = gv * acc[nf][mf][rr*2+1];
                    *reinterpret_cast<float2*>(drow + col) = o;
                }
            }
        }
    }
}

// ---------------- combine: y[t] = yslot[2t] + yslot[2t+1] + bias ------------
__global__ void k_combine(float* __restrict__ out, const float* __restrict__ bias) {
    int idx = blockIdx.x * 256 + threadIdx.x;   // over T*D/4
    int t = idx >> 7;
    int n = (idx & 127) * 4;
    float4 a = *reinterpret_cast<const float4*>(g_yslot + (size_t)(2*t)*D + n);
    float4 b = *reinterpret_cast<const float4*>(g_yslot + (size_t)(2*t+1)*D + n);
    float4 bb = *reinterpret_cast<const float4*>(bias + n);
    float4 y = make_float4(a.x+b.x+bb.x, a.y+b.y+bb.y, a.z+b.z+bb.z, a.w+b.w+bb.w);
    *reinterpret_cast<float4*>(out + (size_t)t*D + n) = y;
}

// ---------------- aux loss finalize -----------------------------------------
__global__ void k_loss(float* out, int out_size) {
    if (out_size <= T*D) return;
    float ps = 0.f;
    for (int e = 0; e < E; e++) ps += g_probs[e];
    float sl = 0.f;
    for (int e = 0; e < E; e++)
        sl += (g_probs[e] / ps) * ((float)g_count[e] / (float)NSLOT);
    float switchloss = (float)E * sl;
    float zloss = g_lsesq / (float)T;
    out[T*D] = switchloss + 0.1f * zloss;
}

// ---------------- launch -----------------------------------------------------
extern "C" void kernel_launch(void* const* d_in, const int* in_sizes, int n_in,
                              void* d_out, int out_size) {
    const float* x     = (const float*)d_in[0];
    const float* wr    = (const float*)d_in[1];
    const float* w_in  = (const float*)d_in[2];
    const float* w_out = (const float*)d_in[3];
    const float* bias  = (const float*)d_in[4];
    float* out = (float*)d_out;

    cudaFuncSetAttribute(k_gemm1, cudaFuncAttributeMaxDynamicSharedMemorySize, G1_SMEM);
    cudaFuncSetAttribute(k_gemm2, cudaFuncAttributeMaxDynamicSharedMemorySize, G2_SMEM);

    uint2* d_x2; uint2* d_win2; uint2* d_wout2;
    cudaGetSymbolAddress((void**)&d_x2, g_x2);
    cudaGetSymbolAddress((void**)&d_win2, g_win2);
    cudaGetSymbolAddress((void**)&d_wout2, g_wout2);

    k_zero<<<1, 32>>>();
    k_split<<<(T*D/4 + 255)/256, 256>>>((const float4*)x, (uint4*)d_x2, T*D/4);
    k_split<<<(E*D*H2/4 + 255)/256, 256>>>((const float4*)w_in, (uint4*)d_win2, E*D*H2/4);
    k_split<<<(E*H*D/4 + 255)/256, 256>>>((const float4*)w_out, (uint4*)d_wout2, E*H*D/4);
    k_router<<<T/256, 256>>>(x, wr);
    k_offsets<<<1, 1>>>();
    k_gemm1<<<dim3(E*16, H/128), 256, G1_SMEM>>>(x);
    k_gemm2<<<dim3(E*16, D/128), 256, G2_SMEM>>>(x);
    k_combine<<<(T*D/4)/256, 256>>>(out, bias);
    k_loss<<<1, 1>>>(out, out_size);
}

// round 10
// speedup vs baseline: 1.8100x; 1.8100x over previous
#include <cuda_runtime.h>
#include <math.h>
#include <stdint.h>

// Problem dims (fixed by the dataset)
#define T    2048
#define D    512
#define H    1024
#define H2   2048
#define E    8
#define NSLOT (T*2)   // 4096

typedef unsigned short ushort_t;

// ---------------- scratch (device globals; no allocations allowed) ----------
__device__ int   g_count[E];
__device__ int   g_off[E];
__device__ int   g_list[E*T];        // per-expert token slot lists (slot = t*2+k)
__device__ float g_gate[NSLOT];      // gate value per slot
__device__ float g_probs[E];         // sum of softmax probs per expert (aux loss)
__device__ float g_lsesq;            // sum of lse^2 (aux loss)
__device__ float g_yslot[(size_t)NSLOT*D];   // gate-scaled expert outputs per slot

// bf16 split operands: hi/lo in separate arrays, k-contiguous for MMA
__device__ ushort_t g_xhi[(size_t)T*D],  g_xlo[(size_t)T*D];            // [t][d]
__device__ ushort_t g_winhi[(size_t)E*H2*D], g_winlo[(size_t)E*H2*D];   // [e][n][k=d]
__device__ ushort_t g_wouthi[(size_t)E*D*H], g_woutlo[(size_t)E*D*H];   // [e][n=d][k=h]
__device__ ushort_t g_hidhi[(size_t)NSLOT*H], g_hidlo[(size_t)NSLOT*H]; // [slot][h]

// ======================= helpers =============================================
__device__ __forceinline__ uint32_t smem_u32(const void* p) {
    uint32_t a;
    asm("{ .reg .u64 t; cvta.to.shared.u64 t, %1; cvt.u32.u64 %0, t; }" : "=r"(a) : "l"(p));
    return a;
}
#define CP16(dst, src) \
    asm volatile("cp.async.cg.shared.global [%0], [%1], 16;" :: "r"(dst), "l"(src) : "memory")
#define CP_COMMIT() asm volatile("cp.async.commit_group;" ::: "memory")
#define CP_WAIT1()  asm volatile("cp.async.wait_group 1;" ::: "memory")
#define CP_WAIT0()  asm volatile("cp.async.wait_group 0;" ::: "memory")

__device__ __forceinline__ ushort_t f2bf(float x) {
    ushort_t r;
    asm("cvt.rn.bf16.f32 %0, %1;" : "=h"(r) : "f"(x));
    return r;
}
__device__ __forceinline__ float bf2f(ushort_t u) {
    return __uint_as_float(((uint32_t)u) << 16);
}
__device__ __forceinline__ void split_bf(float x, ushort_t& hi, ushort_t& lo) {
    hi = f2bf(x);
    lo = f2bf(x - bf2f(hi));
}

#define MMA_BF16(d, a, b0, b1) \
    asm volatile("mma.sync.aligned.m16n8k16.row.col.f32.bf16.bf16.f32 " \
        "{%0,%1,%2,%3},{%4,%5,%6,%7},{%8,%9},{%0,%1,%2,%3};" \
        : "+f"((d)[0]), "+f"((d)[1]), "+f"((d)[2]), "+f"((d)[3]) \
        : "r"((a)[0]), "r"((a)[1]), "r"((a)[2]), "r"((a)[3]), "r"(b0), "r"(b1))

// ---------------- x split (no transpose, streaming) --------------------------
__global__ __launch_bounds__(256) void k_splitx(const float4* __restrict__ src,
                                                ushort_t* __restrict__ dhi,
                                                ushort_t* __restrict__ dlo, int n4) {
    int i = blockIdx.x * 256 + threadIdx.x;
    if (i >= n4) return;
    float4 v = src[i];
    ushort_t h0,h1,h2,h3, l0,l1,l2,l3;
    split_bf(v.x, h0, l0); split_bf(v.y, h1, l1);
    split_bf(v.z, h2, l2); split_bf(v.w, h3, l3);
    uint2 ph, pl;
    ph.x = (uint32_t)h0 | ((uint32_t)h1 << 16);
    ph.y = (uint32_t)h2 | ((uint32_t)h3 << 16);
    pl.x = (uint32_t)l0 | ((uint32_t)l1 << 16);
    pl.y = (uint32_t)l2 | ((uint32_t)l3 << 16);
    *reinterpret_cast<uint2*>(dhi + (size_t)i*4) = ph;
    *reinterpret_cast<uint2*>(dlo + (size_t)i*4) = pl;
}

// ---------------- transpose + split: src [E][R][C] fp32 -> dst [E][C][R] bf16
__global__ __launch_bounds__(256) void k_tsplit(const float* __restrict__ src,
                                                ushort_t* __restrict__ dhi,
                                                ushort_t* __restrict__ dlo,
                                                int R, int C) {
    __shared__ float tile[32][33];
    const int e  = blockIdx.z;
    const int c0 = blockIdx.x * 32;
    const int r0 = blockIdx.y * 32;
    const int j  = threadIdx.x & 31;
    const int i0 = threadIdx.x >> 5;
    const float* s = src + ((size_t)e*R + r0)*C + c0;
#pragma unroll
    for (int rr = 0; rr < 4; rr++) {
        int i = i0 + rr*8;
        tile[i][j] = s[(size_t)i*C + j];
    }
    __syncthreads();
#pragma unroll
    for (int rr = 0; rr < 4; rr++) {
        int i = i0 + rr*8;
        float v = tile[j][i];
        ushort_t hi, lo;
        split_bf(v, hi, lo);
        size_t o = ((size_t)e*C + c0 + i)*R + r0 + j;
        dhi[o] = hi; dlo[o] = lo;
    }
}

// ---------------- zero-init (graph replays must reset state) ----------------
__global__ void k_zero() {
    int t = threadIdx.x;
    if (t < E) { g_count[t] = 0; g_probs[t] = 0.f; }
    if (t == 0) g_lsesq = 0.f;
}

// ---------------- router: logits, top-2, gates, scatter, loss partials ------
__global__ __launch_bounds__(256) void k_router(const float* __restrict__ x,
                                                const float* __restrict__ wr) {
    __shared__ float sw[D*E];
    __shared__ float sp[E];
    __shared__ float slse;
    const int tid = threadIdx.x;
    for (int i = tid; i < D*E; i += 256) sw[i] = wr[i];
    if (tid < E) sp[tid] = 0.f;
    if (tid == 0) slse = 0.f;
    __syncthreads();

    const int t = blockIdx.x * 256 + tid;
    float l[E];
#pragma unroll
    for (int j = 0; j < E; j++) l[j] = 0.f;
    const float4* xr4 = reinterpret_cast<const float4*>(x + (size_t)t * D);
    for (int d4 = 0; d4 < D/4; d4++) {
        float4 v = xr4[d4];
        int d = d4 * 4;
#pragma unroll
        for (int j = 0; j < E; j++) {
            l[j] = fmaf(v.x, sw[(d+0)*E + j], l[j]);
            l[j] = fmaf(v.y, sw[(d+1)*E + j], l[j]);
            l[j] = fmaf(v.z, sw[(d+2)*E + j], l[j]);
            l[j] = fmaf(v.w, sw[(d+3)*E + j], l[j]);
        }
    }

    // top-2, matching jax.lax.top_k tie rule (earliest index wins)
    int i1 = 0; float v1 = l[0];
#pragma unroll
    for (int j = 1; j < E; j++) if (l[j] > v1) { v1 = l[j]; i1 = j; }
    int i2 = (i1 == 0) ? 1 : 0; float v2 = l[i2];
#pragma unroll
    for (int j = 0; j < E; j++) if (j != i1 && l[j] > v2) { v2 = l[j]; i2 = j; }

    float e2 = expf(v2 - v1);
    float inv = 1.f / (1.f + e2);
    float g1 = inv;
    float g2 = e2 * inv;

    float m = v1;
    float s = 0.f;
#pragma unroll
    for (int j = 0; j < E; j++) s += expf(l[j] - m);
    float lse = m + logf(s);
    atomicAdd(&slse, lse * lse);
    float invs = 1.f / s;
#pragma unroll
    for (int j = 0; j < E; j++) atomicAdd(&sp[j], expf(l[j] - m) * invs);

    int p1 = atomicAdd(&g_count[i1], 1);
    g_list[i1*T + p1] = t*2 + 0;
    g_gate[t*2 + 0] = g1;
    int p2 = atomicAdd(&g_count[i2], 1);
    g_list[i2*T + p2] = t*2 + 1;
    g_gate[t*2 + 1] = g2;

    __syncthreads();
    if (tid < E) atomicAdd(&g_probs[tid], sp[tid]);
    if (tid == 0) atomicAdd(&g_lsesq, slse);
}

// ---------------- prefix offsets over E=8 -----------------------------------
__global__ void k_offsets() {
    int o = 0;
    for (int e = 0; e < E; e++) { g_off[e] = o; o += g_count[e]; }
}

// ============================================================================
// GEMM1 (mma.sync bf16 m16n8k16, 3-term split) fused with GLU.
// CTA: 128 gathered tokens x 128 h-cols + matching 128 gate-cols. K=512,
// BK=32, 2-stage cp.async pipeline. A/B: bf16 hi+lo, k-contig, stride 40.
// ============================================================================
#define KST 40                            // padded row stride (ushorts)
#define G1_AHALF (128*KST*2)              // 10240 B per array
#define G1_BHALF (256*KST*2)              // 20480 B per array
#define G1_STG   (2*G1_AHALF + 2*G1_BHALF)  // 61440
#define G1_SMEM  (2*G1_STG)               // 122880

__global__ __launch_bounds__(256, 1) void k_gemm1() {
    const int e   = blockIdx.x >> 4;
    const int rt  = blockIdx.x & 15;
    const int cnt = g_count[e];
    const int m0  = rt * 128;
    if (m0 >= cnt) return;
    const int off = g_off[e];
    const int n0  = blockIdx.y * 128;

    extern __shared__ char smem[];
    __shared__ int s_tok[128];

    const int tid  = threadIdx.x;
    const int wid  = tid >> 5;
    const int lane = tid & 31;
    const int wm   = wid & 3;        // m offset wm*32
    const int wn   = wid >> 2;       // n offset wn*64
    const int tg   = lane & 3;       // thread-in-group
    const int gp   = lane >> 2;      // group id

    if (tid < 128) {
        int i = m0 + tid;
        s_tok[tid] = g_list[e*T + min(i, cnt-1)] >> 1;
    }
    __syncthreads();

    // stage base pointers (ushort indices)
    auto AHI = [&](int s) { return (ushort_t*)(smem + s*G1_STG); };
    auto ALO = [&](int s) { return (ushort_t*)(smem + s*G1_STG + G1_AHALF); };
    auto BHI = [&](int s) { return (ushort_t*)(smem + s*G1_STG + 2*G1_AHALF); };
    auto BLO = [&](int s) { return (ushort_t*)(smem + s*G1_STG + 2*G1_AHALF + G1_BHALF); };

    auto load_stage = [&](int it, int s) {
        const int d0 = it * 32;
        // A: 128 rows x 32 bf16 = 4 chunks/row per array (512 chunks each)
#pragma unroll
        for (int r = 0; r < 2; r++) {
            int c = tid + r*256;
            int row = c >> 2, q = c & 3;
            const ushort_t* sh = g_xhi + (size_t)s_tok[row]*D + d0 + q*8;
            const ushort_t* sl = g_xlo + (size_t)s_tok[row]*D + d0 + q*8;
            CP16(smem_u32(AHI(s) + row*KST + q*8), sh);
            CP16(smem_u32(ALO(s) + row*KST + q*8), sl);
        }
        // B: 256 n-rows x 32 bf16 (1024 chunks each array)
#pragma unroll
        for (int r = 0; r < 4; r++) {
            int c = tid + r*256;
            int nr = c >> 2, q = c & 3;
            int gc = (nr < 128) ? (n0 + nr) : (H + n0 + (nr - 128));
            const ushort_t* sh = g_winhi + ((size_t)e*H2 + gc)*D + d0 + q*8;
            const ushort_t* sl = g_winlo + ((size_t)e*H2 + gc)*D + d0 + q*8;
            CP16(smem_u32(BHI(s) + nr*KST + q*8), sh);
            CP16(smem_u32(BLO(s) + nr*KST + q*8), sl);
        }
        CP_COMMIT();
    };

    float acc[2][8][2][4];
#pragma unroll
    for (int h2 = 0; h2 < 2; h2++)
#pragma unroll
        for (int nf = 0; nf < 8; nf++)
#pragma unroll
            for (int mf = 0; mf < 2; mf++)
#pragma unroll
                for (int r = 0; r < 4; r++) acc[h2][nf][mf][r] = 0.f;

    const int NIT = D / 32;   // 16
    load_stage(0, 0);
    load_stage(1, 1);

    const int rA = wm*32 + gp;

    for (int it = 0; it < NIT; it++) {
        if (it + 1 < NIT) CP_WAIT1(); else CP_WAIT0();
        __syncthreads();
        const int s = it & 1;
        const ushort_t* ah = AHI(s); const ushort_t* al = ALO(s);
        const ushort_t* bh = BHI(s); const ushort_t* bl = BLO(s);
#pragma unroll
        for (int ks = 0; ks < 2; ks++) {
            const int k0 = ks * 16;
            uint32_t ahi[2][4], alo[2][4];
#pragma unroll
            for (int mf = 0; mf < 2; mf++) {
                int rr = rA + mf*16;
                ahi[mf][0] = *(const uint32_t*)(ah + (rr  )*KST + k0 + 2*tg);
                ahi[mf][1] = *(const uint32_t*)(ah + (rr+8)*KST + k0 + 2*tg);
                ahi[mf][2] = *(const uint32_t*)(ah + (rr  )*KST + k0 + 2*tg + 8);
                ahi[mf][3] = *(const uint32_t*)(ah + (rr+8)*KST + k0 + 2*tg + 8);
                alo[mf][0] = *(const uint32_t*)(al + (rr  )*KST + k0 + 2*tg);
                alo[mf][1] = *(const uint32_t*)(al + (rr+8)*KST + k0 + 2*tg);
                alo[mf][2] = *(const uint32_t*)(al + (rr  )*KST + k0 + 2*tg + 8);
                alo[mf][3] = *(const uint32_t*)(al + (rr+8)*KST + k0 + 2*tg + 8);
            }
#pragma unroll
            for (int h2 = 0; h2 < 2; h2++) {
#pragma unroll
                for (int nf = 0; nf < 8; nf++) {
                    int n = h2*128 + wn*64 + nf*8 + gp;
                    uint32_t bh0 = *(const uint32_t*)(bh + n*KST + k0 + 2*tg);
                    uint32_t bh1 = *(const uint32_t*)(bh + n*KST + k0 + 2*tg + 8);
                    uint32_t bl0 = *(const uint32_t*)(bl + n*KST + k0 + 2*tg);
                    uint32_t bl1 = *(const uint32_t*)(bl + n*KST + k0 + 2*tg + 8);
                    MMA_BF16(acc[h2][nf][0], ahi[0], bh0, bh1);
                    MMA_BF16(acc[h2][nf][1], ahi[1], bh0, bh1);
                    MMA_BF16(acc[h2][nf][0], ahi[0], bl0, bl1);
                    MMA_BF16(acc[h2][nf][1], ahi[1], bl0, bl1);
                    MMA_BF16(acc[h2][nf][0], alo[0], bh0, bh1);
                    MMA_BF16(acc[h2][nf][1], alo[1], bh0, bh1);
                }
            }
        }
        __syncthreads();
        if (it + 2 < NIT) load_stage(it + 2, s);
    }

    // Epilogue: h = silu(a)*g, split to bf16 hi/lo, write g_hid
#pragma unroll
    for (int mf = 0; mf < 2; mf++) {
#pragma unroll
        for (int rr = 0; rr < 2; rr++) {
            int m = m0 + wm*32 + mf*16 + gp + rr*8;
            if (m < cnt) {
                size_t rowb = (size_t)(off + m)*H + n0;
#pragma unroll
                for (int nf = 0; nf < 8; nf++) {
                    int col = wn*64 + nf*8 + 2*tg;
                    float a0 = acc[0][nf][mf][rr*2+0], g0v = acc[1][nf][mf][rr*2+0];
                    float a1 = acc[0][nf][mf][rr*2+1], g1v = acc[1][nf][mf][rr*2+1];
                    float h0 = (a0 / (1.f + expf(-a0))) * g0v;
                    float h1 = (a1 / (1.f + expf(-a1))) * g1v;
                    ushort_t hh0, hl0, hh1, hl1;
                    split_bf(h0, hh0, hl0);
                    split_bf(h1, hh1, hl1);
                    *(uint32_t*)(g_hidhi + rowb + col) = (uint32_t)hh0 | ((uint32_t)hh1 << 16);
                    *(uint32_t*)(g_hidlo + rowb + col) = (uint32_t)hl0 | ((uint32_t)hl1 << 16);
                }
            }
        }
    }
}

// ============================================================================
// GEMM2 (mma.sync bf16, 3-term): yslot = gate * (hidden @ w_out)
// CTA: 128 slots x 128 out-cols. K=1024, BK=32, 2-stage pipeline.
// ============================================================================
#define G2_AHALF (128*KST*2)              // 10240
#define G2_BHALF (128*KST*2)              // 10240
#define G2_STG   (2*G2_AHALF + 2*G2_BHALF)  // 40960
#define G2_SMEM  (2*G2_STG)               // 81920

__global__ __launch_bounds__(256, 1) void k_gemm2() {
    const int e   = blockIdx.x >> 4;
    const int rt  = blockIdx.x & 15;
    const int cnt = g_count[e];
    const int m0  = rt * 128;
    if (m0 >= cnt) return;
    const int off = g_off[e];
    const int n0  = blockIdx.y * 128;
    const int cmax = cnt - 1;

    extern __shared__ char smem[];
    const int tid  = threadIdx.x;
    const int wid  = tid >> 5;
    const int lane = tid & 31;
    const int wm   = wid & 3;
    const int wn   = wid >> 2;
    const int tg   = lane & 3;
    const int gp   = lane >> 2;

    auto AHI = [&](int s) { return (ushort_t*)(smem + s*G2_STG); };
    auto ALO = [&](int s) { return (ushort_t*)(smem + s*G2_STG + G2_AHALF); };
    auto BHI = [&](int s) { return (ushort_t*)(smem + s*G2_STG + 2*G2_AHALF); };
    auto BLO = [&](int s) { return (ushort_t*)(smem + s*G2_STG + 2*G2_AHALF + G2_BHALF); };

    auto load_stage = [&](int it, int s) {
        const int h0 = it * 32;
#pragma unroll
        for (int r = 0; r < 2; r++) {
            int c = tid + r*256;
            int row = c >> 2, q = c & 3;
            int gr = off + min(m0 + row, cmax);
            CP16(smem_u32(AHI(s) + row*KST + q*8), g_hidhi + (size_t)gr*H + h0 + q*8);
            CP16(smem_u32(ALO(s) + row*KST + q*8), g_hidlo + (size_t)gr*H + h0 + q*8);
        }
#pragma unroll
        for (int r = 0; r < 2; r++) {
            int c = tid + r*256;
            int nr = c >> 2, q = c & 3;
            int gc = n0 + nr;
            CP16(smem_u32(BHI(s) + nr*KST + q*8), g_wouthi + ((size_t)e*D + gc)*H + h0 + q*8);
            CP16(smem_u32(BLO(s) + nr*KST + q*8), g_woutlo + ((size_t)e*D + gc)*H + h0 + q*8);
        }
        CP_COMMIT();
    };

    float acc[8][2][4];
#pragma unroll
    for (int nf = 0; nf < 8; nf++)
#pragma unroll
        for (int mf = 0; mf < 2; mf++)
#pragma unroll
            for (int r = 0; r < 4; r++) acc[nf][mf][r] = 0.f;

    const int NIT = H / 32;   // 32
    load_stage(0, 0);
    load_stage(1, 1);

    const int rA = wm*32 + gp;

    for (int it = 0; it < NIT; it++) {
        if (it + 1 < NIT) CP_WAIT1(); else CP_WAIT0();
        __syncthreads();
        const int s = it & 1;
        const ushort_t* ah = AHI(s); const ushort_t* al = ALO(s);
        const ushort_t* bh = BHI(s); const ushort_t* bl = BLO(s);
#pragma unroll
        for (int ks = 0; ks < 2; ks++) {
            const int k0 = ks * 16;
            uint32_t ahi[2][4], alo[2][4];
#pragma unroll
            for (int mf = 0; mf < 2; mf++) {
                int rr = rA + mf*16;
                ahi[mf][0] = *(const uint32_t*)(ah + (rr  )*KST + k0 + 2*tg);
                ahi[mf][1] = *(const uint32_t*)(ah + (rr+8)*KST + k0 + 2*tg);
                ahi[mf][2] = *(const uint32_t*)(ah + (rr  )*KST + k0 + 2*tg + 8);
                ahi[mf][3] = *(const uint32_t*)(ah + (rr+8)*KST + k0 + 2*tg + 8);
                alo[mf][0] = *(const uint32_t*)(al + (rr  )*KST + k0 + 2*tg);
                alo[mf][1] = *(const uint32_t*)(al + (rr+8)*KST + k0 + 2*tg);
                alo[mf][2] = *(const uint32_t*)(al + (rr  )*KST + k0 + 2*tg + 8);
                alo[mf][3] = *(const uint32_t*)(al + (rr+8)*KST + k0 + 2*tg + 8);
            }
#pragma unroll
            for (int nf = 0; nf < 8; nf++) {
                int n = wn*64 + nf*8 + gp;
                uint32_t bh0 = *(const uint32_t*)(bh + n*KST + k0 + 2*tg);
                uint32_t bh1 = *(const uint32_t*)(bh + n*KST + k0 + 2*tg + 8);
                uint32_t bl0 = *(const uint32_t*)(bl + n*KST + k0 + 2*tg);
                uint32_t bl1 = *(const uint32_t*)(bl + n*KST + k0 + 2*tg + 8);
                MMA_BF16(acc[nf][0], ahi[0], bh0, bh1);
                MMA_BF16(acc[nf][1], ahi[1], bh0, bh1);
                MMA_BF16(acc[nf][0], ahi[0], bl0, bl1);
                MMA_BF16(acc[nf][1], ahi[1], bl0, bl1);
                MMA_BF16(acc[nf][0], alo[0], bh0, bh1);
                MMA_BF16(acc[nf][1], alo[1], bh0, bh1);
            }
        }
        __syncthreads();
        if (it + 2 < NIT) load_stage(it + 2, s);
    }

    // Epilogue: scale by gate, scatter to yslot
#pragma unroll
    for (int mf = 0; mf < 2; mf++) {
#pragma unroll
        for (int rr = 0; rr < 2; rr++) {
            int m = m0 + wm*32 + mf*16 + gp + rr*8;
            if (m < cnt) {
                int slot = g_list[e*T + m];
                float gv = g_gate[slot];
                float* drow = g_yslot + (size_t)slot*D + n0;
#pragma unroll
                for (int nf = 0; nf < 8; nf++) {
                    int col = wn*64 + nf*8 + 2*tg;
                    float2 o;
                    o.x = gv * acc[nf][mf][rr*2+0];
                    o.y = gv * acc[nf][mf][rr*2+1];
                    *reinterpret_cast<float2*>(drow + col) = o;
                }
            }
        }
    }
}

// ---------------- combine: y[t] = yslot[2t] + yslot[2t+1] + bias ------------
__global__ void k_combine(float* __restrict__ out, const float* __restrict__ bias) {
    int idx = blockIdx.x * 256 + threadIdx.x;   // over T*D/4
    int t = idx >> 7;
    int n = (idx & 127) * 4;
    float4 a = *reinterpret_cast<const float4*>(g_yslot + (size_t)(2*t)*D + n);
    float4 b = *reinterpret_cast<const float4*>(g_yslot + (size_t)(2*t+1)*D + n);
    float4 bb = *reinterpret_cast<const float4*>(bias + n);
    float4 y = make_float4(a.x+b.x+bb.x, a.y+b.y+bb.y, a.z+b.z+bb.z, a.w+b.w+bb.w);
    *reinterpret_cast<float4*>(out + (size_t)t*D + n) = y;
}

// ---------------- aux loss finalize -----------------------------------------
__global__ void k_loss(float* out, int out_size) {
    if (out_size <= T*D) return;
    float ps = 0.f;
    for (int e = 0; e < E; e++) ps += g_probs[e];
    float sl = 0.f;
    for (int e = 0; e < E; e++)
        sl += (g_probs[e] / ps) * ((float)g_count[e] / (float)NSLOT);
    float switchloss = (float)E * sl;
    float zloss = g_lsesq / (float)T;
    out[T*D] = switchloss + 0.1f * zloss;
}

// ---------------- launch -----------------------------------------------------
extern "C" void kernel_launch(void* const* d_in, const int* in_sizes, int n_in,
                              void* d_out, int out_size) {
    const float* x     = (const float*)d_in[0];
    const float* wr    = (const float*)d_in[1];
    const float* w_in  = (const float*)d_in[2];
    const float* w_out = (const float*)d_in[3];
    const float* bias  = (const float*)d_in[4];
    float* out = (float*)d_out;

    cudaFuncSetAttribute(k_gemm1, cudaFuncAttributeMaxDynamicSharedMemorySize, G1_SMEM);
    cudaFuncSetAttribute(k_gemm2, cudaFuncAttributeMaxDynamicSharedMemorySize, G2_SMEM);

    ushort_t *d_xhi, *d_xlo, *d_winhi, *d_winlo, *d_wouthi, *d_woutlo;
    cudaGetSymbolAddress((void**)&d_xhi, g_xhi);
    cudaGetSymbolAddress((void**)&d_xlo, g_xlo);
    cudaGetSymbolAddress((void**)&d_winhi, g_winhi);
    cudaGetSymbolAddress((void**)&d_winlo, g_winlo);
    cudaGetSymbolAddress((void**)&d_wouthi, g_wouthi);
    cudaGetSymbolAddress((void**)&d_woutlo, g_woutlo);

    k_zero<<<1, 32>>>();
    k_splitx<<<(T*D/4)/256, 256>>>((const float4*)x, d_xhi, d_xlo, T*D/4);
    // w_in: [E][D(512)][H2(2048)] -> [E][H2][D]
    k_tsplit<<<dim3(H2/32, D/32, E), 256>>>(w_in, d_winhi, d_winlo, D, H2);
    // w_out: [E][H(1024)][D(512)] -> [E][D][H]
    k_tsplit<<<dim3(D/32, H/32, E), 256>>>(w_out, d_wouthi, d_woutlo, H, D);
    k_router<<<T/256, 256>>>(x, wr);
    k_offsets<<<1, 1>>>();
    k_gemm1<<<dim3(E*16, H/128), 256, G1_SMEM>>>();
    k_gemm2<<<dim3(E*16, D/128), 256, G2_SMEM>>>();
    k_combine<<<(T*D/4)/256, 256>>>(out, bias);
    k_loss<<<1, 1>>>(out, out_size);
}